// round 3
// baseline (speedup 1.0000x reference)
#include <cuda_runtime.h>
#include <math.h>
#include <float.h>
#include <stdint.h>

#define S   4096
#define MD  2048
#define E   32
#define CAP 256
#define CW_ELEMS ((size_t)S * E * CAP)   // 33554432

// ---------------- device scratch (no allocations allowed) ----------------
__device__ float g_logits[S * E];
__device__ int   g_top_i1[S];
__device__ int   g_top_i2[S];
__device__ float g_top_v1[S];
__device__ float g_top_v2[S];
__device__ float g_top_g1[S];
__device__ float g_top_g2[S];
__device__ int   g_slot[S * 2];

#define NB2 128
__device__ float g_pgsum[NB2 * E];
__device__ int   g_pcnt[NB2 * E];

// ---------------- K1: fused GEMM (logits = x @ wg^T) + zero-fill ----------
#define GEMM_BLOCKS 128
#define FILL_BLOCKS 896
#define K1_THREADS  128
#define KC 128
#define LD4 33   // float4 row stride (132 floats = 528B, shifts banks by 4)

__global__ __launch_bounds__(K1_THREADS)
void k1_gemm_fill(const float* __restrict__ x, const float* __restrict__ wg,
                  float* __restrict__ out, long long out_elems)
{
    if (blockIdx.x >= GEMM_BLOCKS) {
        // ---- zero-fill the entire output buffer ----
        long long n4 = out_elems >> 2;
        float4 z = make_float4(0.f, 0.f, 0.f, 0.f);
        float4* o4 = (float4*)out;
        long long idx    = (long long)(blockIdx.x - GEMM_BLOCKS) * K1_THREADS + threadIdx.x;
        long long stride = (long long)FILL_BLOCKS * K1_THREADS;
        for (long long i = idx; i < n4; i += stride) o4[i] = z;
        if (blockIdx.x == GEMM_BLOCKS) {
            long long tail = n4 << 2;
            long long rem  = out_elems - tail;
            if ((long long)threadIdx.x < rem) out[tail + threadIdx.x] = 0.f;
        }
        return;
    }

    // ---- GEMM: 32 tokens x 32 experts per block, K-chunks of 128 ----
    __shared__ float4 xs[32 * LD4];
    __shared__ float4 ws[32 * LD4];

    const int tid = threadIdx.x;
    const int tx  = tid & 7;    // expert group (4 experts)
    const int ty  = tid >> 3;   // token group  (2 tokens), 0..15
    const int t0  = blockIdx.x * 32;

    float acc[2][4];
#pragma unroll
    for (int i = 0; i < 2; i++)
#pragma unroll
        for (int j = 0; j < 4; j++) acc[i][j] = 0.f;

    const float4* x4 = (const float4*)x;
    const float4* w4 = (const float4*)wg;

    for (int kc = 0; kc < MD; kc += KC) {
        const int kc4 = kc >> 2;
        for (int i = tid; i < 32 * 32; i += K1_THREADS) {
            int r = i >> 5, c = i & 31;
            xs[r * LD4 + c] = x4[(size_t)(t0 + r) * (MD / 4) + kc4 + c];
            ws[r * LD4 + c] = w4[(size_t)r       * (MD / 4) + kc4 + c];
        }
        __syncthreads();

#pragma unroll 8
        for (int k4 = 0; k4 < 32; k4++) {
            float4 a0 = xs[(2 * ty)     * LD4 + k4];
            float4 a1 = xs[(2 * ty + 1) * LD4 + k4];
#pragma unroll
            for (int j = 0; j < 4; j++) {
                float4 b = ws[(4 * tx + j) * LD4 + k4];
                acc[0][j] = fmaf(a0.x, b.x, fmaf(a0.y, b.y, fmaf(a0.z, b.z, fmaf(a0.w, b.w, acc[0][j]))));
                acc[1][j] = fmaf(a1.x, b.x, fmaf(a1.y, b.y, fmaf(a1.z, b.z, fmaf(a1.w, b.w, acc[1][j]))));
            }
        }
        __syncthreads();
    }

#pragma unroll
    for (int i = 0; i < 2; i++)
#pragma unroll
        for (int j = 0; j < 4; j++)
            g_logits[(size_t)(t0 + 2 * ty + i) * E + (4 * tx + j)] = acc[i][j];
}

// ---------------- K2: softmax + top-2 + deterministic partial sums --------
__global__ __launch_bounds__(1024)
void k2_topk()
{
    const int warp = threadIdx.x >> 5;
    const int lane = threadIdx.x & 31;
    const int t = blockIdx.x * 32 + warp;

    float l = g_logits[(size_t)t * E + lane];

    // top-1 (tie -> lower index, matching jax.lax.top_k)
    float v1 = l; int i1 = lane;
#pragma unroll
    for (int off = 16; off; off >>= 1) {
        float ov = __shfl_xor_sync(0xffffffffu, v1, off);
        int   oi = __shfl_xor_sync(0xffffffffu, i1, off);
        if (ov > v1 || (ov == v1 && oi < i1)) { v1 = ov; i1 = oi; }
    }
    // top-2
    float l2 = (lane == i1) ? -FLT_MAX : l;
    float v2 = l2; int i2 = lane;
#pragma unroll
    for (int off = 16; off; off >>= 1) {
        float ov = __shfl_xor_sync(0xffffffffu, v2, off);
        int   oi = __shfl_xor_sync(0xffffffffu, i2, off);
        if (ov > v2 || (ov == v2 && oi < i2)) { v2 = ov; i2 = oi; }
    }

    // softmax over the 32 logits
    float p = expf(l - v1);
    float sum = p;
#pragma unroll
    for (int off = 16; off; off >>= 1) sum += __shfl_xor_sync(0xffffffffu, sum, off);
    float gate = p / sum;

    float g1v = __shfl_sync(0xffffffffu, gate, i1);
    float g2v = __shfl_sync(0xffffffffu, gate, i2);

    if (lane == 0) {
        g_top_i1[t] = i1;  g_top_i2[t] = i2;
        g_top_v1[t] = v1;  g_top_v2[t] = v2;
        g_top_g1[t] = g1v; g_top_g2[t] = g2v;
        g_slot[2 * t]     = -1;
        g_slot[2 * t + 1] = -1;
    }

    // deterministic per-block reduction of gates / counts
    __shared__ float gm[32][33];
    __shared__ int   im[32];
    gm[warp][lane] = gate;
    if (lane == 0) im[warp] = i1 | (i2 << 8);
    __syncthreads();

    if (warp == 0) {
        float s = 0.f; int c = 0;
#pragma unroll 8
        for (int w = 0; w < 32; w++) {
            s += gm[w][lane];
            int pk = im[w];
            c += ((pk & 255) == lane) + ((pk >> 8) == lane);
        }
        g_pgsum[blockIdx.x * E + lane] = s;
        g_pcnt [blockIdx.x * E + lane] = c;
    }
}

// ---------------- K3: per-expert capacity filter + slot assignment --------
__global__ __launch_bounds__(256)
void k3_capacity()
{
    const int e = blockIdx.x;
    __shared__ float vals[S];
    __shared__ int   s_cnt;
    __shared__ float s_thr;
    __shared__ int   warp_tot[8];
    __shared__ int   s_running;

    if (threadIdx.x == 0) { s_cnt = 0; s_running = 0; }
    __syncthreads();

    // gather positive selected logits for this expert
    for (int t = threadIdx.x; t < S; t += 256) {
        int i1 = g_top_i1[t], i2 = g_top_i2[t];
        float v; int hit = 0;
        if (i1 == e)      { v = g_top_v1[t]; hit = 1; }
        else if (i2 == e) { v = g_top_v2[t]; hit = 1; }
        else v = 0.f;
        if (hit && v > 0.f) {
            int p = atomicAdd(&s_cnt, 1);
            vals[p] = v;
        }
    }
    __syncthreads();

    int n = s_cnt;
    if (n <= CAP) {
        if (threadIdx.x == 0) s_thr = -FLT_MAX;
        __syncthreads();
    } else {
        int n2 = 1; while (n2 < n) n2 <<= 1;
        for (int i = n + threadIdx.x; i < n2; i += 256) vals[i] = -FLT_MAX;
        __syncthreads();
        // bitonic sort, descending
        for (int k = 2; k <= n2; k <<= 1) {
            for (int j = k >> 1; j > 0; j >>= 1) {
                for (int i = threadIdx.x; i < n2; i += 256) {
                    int ixj = i ^ j;
                    if (ixj > i) {
                        float a = vals[i], b = vals[ixj];
                        bool desc = ((i & k) == 0);
                        if (desc ? (a < b) : (a > b)) { vals[i] = b; vals[ixj] = a; }
                    }
                }
                __syncthreads();
            }
        }
        if (threadIdx.x == 0) s_thr = vals[CAP - 1];
        __syncthreads();
    }
    float thr = s_thr;

    // token-order scan: assign cumulative slots
    const int lane = threadIdx.x & 31;
    const int w    = threadIdx.x >> 5;
    for (int base = 0; base < S; base += 256) {
        int t = base + threadIdx.x;
        int i1 = g_top_i1[t], i2 = g_top_i2[t];
        int j = (i1 == e) ? 0 : ((i2 == e) ? 1 : -1);
        float v = (j == 0) ? g_top_v1[t] : ((j == 1) ? g_top_v2[t] : 0.f);
        int kept = (j >= 0 && v > 0.f && v >= thr) ? 1 : 0;

        unsigned bal = __ballot_sync(0xffffffffu, kept);
        int pre = __popc(bal & ((1u << lane) - 1u));
        if (lane == 31) warp_tot[w] = pre + kept;
        __syncthreads();

        int woff = 0;
#pragma unroll
        for (int ww = 0; ww < 8; ww++) woff += (ww < w) ? warp_tot[ww] : 0;
        int slot = s_running + woff + pre;
        if (kept) g_slot[2 * t + j] = slot;
        __syncthreads();

        if (threadIdx.x == 0) {
            int tot = 0;
#pragma unroll
            for (int ww = 0; ww < 8; ww++) tot += warp_tot[ww];
            s_running += tot;
        }
        __syncthreads();
    }
}

// ---------------- K4: scatter combine/dispatch + l_aux + exp_counts -------
__global__ __launch_bounds__(256)
void k4_final(float* __restrict__ laux, float* __restrict__ cw,
              float* __restrict__ dm,   float* __restrict__ ec)
{
    // l_aux + exp_counts on block 0, warp 0
    if (blockIdx.x == 0 && threadIdx.x < 32) {
        int e = threadIdx.x;
        float s = 0.f; int c = 0;
        for (int b = 0; b < NB2; b++) { s += g_pgsum[b * E + e]; c += g_pcnt[b * E + e]; }
        if (ec) ec[e] = (float)c;
        float prod = (s / (float)S) * ((float)c / (float)S);
#pragma unroll
        for (int off = 16; off; off >>= 1) prod += __shfl_xor_sync(0xffffffffu, prod, off);
        if (e == 0 && laux) laux[0] = prod * ((float)(E * E) / 2.0f / (float)E); // = prod*16
    }

    int t = blockIdx.x * 256 + threadIdx.x;
    if (t >= S) return;

    int   i1 = g_top_i1[t], i2 = g_top_i2[t];
    float g1 = g_top_g1[t], g2 = g_top_g2[t];
    int   s1 = g_slot[2 * t], s2 = g_slot[2 * t + 1];
    bool  k1 = (s1 >= 0), k2 = (s2 >= 0);

    float denom = (k1 ? g1 : 0.f) + (k2 ? g2 : 0.f);
    if (denom <= 0.f) return;

    int c = (k1 ? s1 : 0) + (k2 ? s2 : 0);  // locations_s = SUM of slots (ref semantics)
    if (c >= CAP) return;                    // one_hot out of range -> all zeros

    if (k1 && cw) {
        size_t o = ((size_t)t * E + i1) * CAP + c;
        cw[o] = g1 / denom;
        if (dm) dm[o] = 1.0f;
    }
    if (k2 && cw) {
        size_t o = ((size_t)t * E + i2) * CAP + c;
        cw[o] = g2 / denom;
        if (dm) dm[o] = 1.0f;
    }
}

// ---------------- launch ---------------------------------------------------
extern "C" void kernel_launch(void* const* d_in, const int* in_sizes, int n_in,
                              void* d_out, int out_size)
{
    const float* x  = (const float*)d_in[0];
    const float* wg = (const float*)d_in[1];
    float* out = (float*)d_out;

    const long long CW = (long long)CW_ELEMS;
    float *laux = nullptr, *cw = nullptr, *dm = nullptr, *ec = nullptr;

    long long osz = (long long)out_size;
    if (osz == 1 + 2 * CW + 32) {
        // [l_aux, combine_weights, dispatch_mask, exp_counts] flattened f32
        laux = out;
        cw   = out + 1;
        dm   = out + 1 + CW;
        ec   = out + 1 + 2 * CW;
    } else if (osz == 2 * CW) {
        cw = out; dm = out + CW;
    } else if (osz == CW) {
        cw = out;
    } else {
        // unknown layout: assume reference tuple order anyway
        laux = out;
        cw   = out + 1;
        if (osz > 1 + CW)     dm = out + 1 + CW;
        if (osz > 1 + 2 * CW) ec = out + 1 + 2 * CW;
    }

    k1_gemm_fill<<<GEMM_BLOCKS + FILL_BLOCKS, K1_THREADS>>>(x, wg, out, osz);
    k2_topk<<<NB2, 1024>>>();
    k3_capacity<<<E, 256>>>();
    k4_final<<<(S + 255) / 256, 256>>>(laux, cw, dm, ec);
}

// round 4
// speedup vs baseline: 1.0408x; 1.0408x over previous
#include <cuda_runtime.h>
#include <math.h>
#include <float.h>
#include <stdint.h>

#define S   4096
#define MD  2048
#define E   32
#define CAP 256
#define CW_ELEMS ((size_t)S * E * CAP)   // 33554432

// ---------------- device scratch (no allocations allowed) ----------------
__device__ int   g_top_i1[S];
__device__ int   g_top_i2[S];
__device__ float g_top_v1[S];
__device__ float g_top_v2[S];
__device__ float g_top_g1[S];
__device__ float g_top_g2[S];
__device__ int   g_slot[S * 2];

#define GEMM_BLOCKS 128
#define NB2 GEMM_BLOCKS
__device__ float g_pgsum[NB2 * E];
__device__ int   g_pcnt[NB2 * E];

// ---------------- K1: fused GEMM + top2/softmax epilogue + zero-fill ------
#define FILL_BLOCKS 896
#define K1_THREADS  128
#define KC 128
#define LD4 33   // float4 row stride (shifts banks)

__global__ __launch_bounds__(K1_THREADS)
void k1_gemm_fill(const float* __restrict__ x, const float* __restrict__ wg,
                  float* __restrict__ out, long long out_elems)
{
    if (blockIdx.x >= GEMM_BLOCKS) {
        // ---- streaming zero-fill of the entire output buffer ----
        long long n4 = out_elems >> 2;
        float4 z = make_float4(0.f, 0.f, 0.f, 0.f);
        float4* o4 = (float4*)out;
        long long idx    = (long long)(blockIdx.x - GEMM_BLOCKS) * K1_THREADS + threadIdx.x;
        long long stride = (long long)FILL_BLOCKS * K1_THREADS;
        long long i = idx;
        for (; i + 3 * stride < n4; i += 4 * stride) {
            __stcs(o4 + i,              z);
            __stcs(o4 + i +     stride, z);
            __stcs(o4 + i + 2 * stride, z);
            __stcs(o4 + i + 3 * stride, z);
        }
        for (; i < n4; i += stride) __stcs(o4 + i, z);
        if (blockIdx.x == GEMM_BLOCKS) {
            long long tail = n4 << 2;
            long long rem  = out_elems - tail;
            if ((long long)threadIdx.x < rem) out[tail + threadIdx.x] = 0.f;
        }
        return;
    }

    // ---- GEMM: 32 tokens x 32 experts per block, K-chunks of 128 ----
    __shared__ float4 xs[32 * LD4];
    __shared__ float4 ws[32 * LD4];
    __shared__ float  ps[4][32];
    __shared__ int    pc[4][32];

    const int tid = threadIdx.x;
    const int tx  = tid & 7;    // expert group (4 experts)
    const int ty  = tid >> 3;   // token group  (2 tokens), 0..15
    const int t0  = blockIdx.x * 32;

    float acc[2][4];
#pragma unroll
    for (int i = 0; i < 2; i++)
#pragma unroll
        for (int j = 0; j < 4; j++) acc[i][j] = 0.f;

    const float4* x4 = (const float4*)x;
    const float4* w4 = (const float4*)wg;

    for (int kc = 0; kc < MD; kc += KC) {
        const int kc4 = kc >> 2;
        for (int i = tid; i < 32 * 32; i += K1_THREADS) {
            int r = i >> 5, c = i & 31;
            xs[r * LD4 + c] = x4[(size_t)(t0 + r) * (MD / 4) + kc4 + c];
            ws[r * LD4 + c] = w4[(size_t)r       * (MD / 4) + kc4 + c];
        }
        __syncthreads();

#pragma unroll 8
        for (int k4 = 0; k4 < 32; k4++) {
            float4 a0 = xs[(2 * ty)     * LD4 + k4];
            float4 a1 = xs[(2 * ty + 1) * LD4 + k4];
#pragma unroll
            for (int j = 0; j < 4; j++) {
                float4 b = ws[(4 * tx + j) * LD4 + k4];
                acc[0][j] = fmaf(a0.x, b.x, fmaf(a0.y, b.y, fmaf(a0.z, b.z, fmaf(a0.w, b.w, acc[0][j]))));
                acc[1][j] = fmaf(a1.x, b.x, fmaf(a1.y, b.y, fmaf(a1.z, b.z, fmaf(a1.w, b.w, acc[1][j]))));
            }
        }
        __syncthreads();
    }

    // ---- epilogue: stash logits in smem (reuse xs), then top2+softmax ----
    float* lg = (float*)xs;   // [32][33] floats
#pragma unroll
    for (int i = 0; i < 2; i++)
#pragma unroll
        for (int j = 0; j < 4; j++)
            lg[(2 * ty + i) * 33 + (4 * tx + j)] = acc[i][j];
    __syncthreads();

    const int warp = tid >> 5;
    const int lane = tid & 31;
    float gsum = 0.f;
    int   gcnt = 0;

#pragma unroll
    for (int k = 0; k < 8; k++) {
        const int tl = warp * 8 + k;
        const int t  = t0 + tl;
        float l = lg[tl * 33 + lane];

        // top-1 (tie -> lower index, matching jax.lax.top_k)
        float v1 = l; int i1 = lane;
#pragma unroll
        for (int off = 16; off; off >>= 1) {
            float ov = __shfl_xor_sync(0xffffffffu, v1, off);
            int   oi = __shfl_xor_sync(0xffffffffu, i1, off);
            if (ov > v1 || (ov == v1 && oi < i1)) { v1 = ov; i1 = oi; }
        }
        // top-2
        float l2 = (lane == i1) ? -FLT_MAX : l;
        float v2 = l2; int i2 = lane;
#pragma unroll
        for (int off = 16; off; off >>= 1) {
            float ov = __shfl_xor_sync(0xffffffffu, v2, off);
            int   oi = __shfl_xor_sync(0xffffffffu, i2, off);
            if (ov > v2 || (ov == v2 && oi < i2)) { v2 = ov; i2 = oi; }
        }

        // softmax over the 32 logits
        float p = expf(l - v1);
        float sum = p;
#pragma unroll
        for (int off = 16; off; off >>= 1) sum += __shfl_xor_sync(0xffffffffu, sum, off);
        float gate = p / sum;

        float g1v = __shfl_sync(0xffffffffu, gate, i1);
        float g2v = __shfl_sync(0xffffffffu, gate, i2);

        if (lane == 0) {
            g_top_i1[t] = i1;  g_top_i2[t] = i2;
            g_top_v1[t] = v1;  g_top_v2[t] = v2;
            g_top_g1[t] = g1v; g_top_g2[t] = g2v;
            g_slot[2 * t]     = -1;
            g_slot[2 * t + 1] = -1;
        }

        gsum += gate;
        gcnt += (i1 == lane) + (i2 == lane);
    }

    ps[warp][lane] = gsum;
    pc[warp][lane] = gcnt;
    __syncthreads();
    if (tid < 32) {
        float s = ps[0][tid] + ps[1][tid] + ps[2][tid] + ps[3][tid];
        int   c = pc[0][tid] + pc[1][tid] + pc[2][tid] + pc[3][tid];
        g_pgsum[blockIdx.x * E + tid] = s;
        g_pcnt [blockIdx.x * E + tid] = c;
    }
}

// ---------------- K3: per-expert capacity filter + slot assignment --------
__global__ __launch_bounds__(256)
void k3_capacity()
{
    const int e = blockIdx.x;
    __shared__ float vals[S];
    __shared__ int   s_cnt;
    __shared__ float s_thr;
    __shared__ int   warp_tot[8];
    __shared__ int   s_running;

    if (threadIdx.x == 0) { s_cnt = 0; s_running = 0; }
    __syncthreads();

    // gather positive selected logits for this expert
    for (int t = threadIdx.x; t < S; t += 256) {
        int i1 = g_top_i1[t], i2 = g_top_i2[t];
        float v; int hit = 0;
        if (i1 == e)      { v = g_top_v1[t]; hit = 1; }
        else if (i2 == e) { v = g_top_v2[t]; hit = 1; }
        else v = 0.f;
        if (hit && v > 0.f) {
            int p = atomicAdd(&s_cnt, 1);
            vals[p] = v;
        }
    }
    __syncthreads();

    int n = s_cnt;
    if (n <= CAP) {
        if (threadIdx.x == 0) s_thr = -FLT_MAX;
        __syncthreads();
    } else {
        int n2 = 1; while (n2 < n) n2 <<= 1;
        for (int i = n + threadIdx.x; i < n2; i += 256) vals[i] = -FLT_MAX;
        __syncthreads();
        // bitonic sort, descending
        for (int k = 2; k <= n2; k <<= 1) {
            for (int j = k >> 1; j > 0; j >>= 1) {
                for (int i = threadIdx.x; i < n2; i += 256) {
                    int ixj = i ^ j;
                    if (ixj > i) {
                        float a = vals[i], b = vals[ixj];
                        bool desc = ((i & k) == 0);
                        if (desc ? (a < b) : (a > b)) { vals[i] = b; vals[ixj] = a; }
                    }
                }
                __syncthreads();
            }
        }
        if (threadIdx.x == 0) s_thr = vals[CAP - 1];
        __syncthreads();
    }
    float thr = s_thr;

    // token-order scan: assign cumulative slots
    const int lane = threadIdx.x & 31;
    const int w    = threadIdx.x >> 5;
    for (int base = 0; base < S; base += 256) {
        int t = base + threadIdx.x;
        int i1 = g_top_i1[t], i2 = g_top_i2[t];
        int j = (i1 == e) ? 0 : ((i2 == e) ? 1 : -1);
        float v = (j == 0) ? g_top_v1[t] : ((j == 1) ? g_top_v2[t] : 0.f);
        int kept = (j >= 0 && v > 0.f && v >= thr) ? 1 : 0;

        unsigned bal = __ballot_sync(0xffffffffu, kept);
        int pre = __popc(bal & ((1u << lane) - 1u));
        if (lane == 31) warp_tot[w] = pre + kept;
        __syncthreads();

        int woff = 0;
#pragma unroll
        for (int ww = 0; ww < 8; ww++) woff += (ww < w) ? warp_tot[ww] : 0;
        int slot = s_running + woff + pre;
        if (kept) g_slot[2 * t + j] = slot;
        __syncthreads();

        if (threadIdx.x == 0) {
            int tot = 0;
#pragma unroll
            for (int ww = 0; ww < 8; ww++) tot += warp_tot[ww];
            s_running += tot;
        }
        __syncthreads();
    }
}

// ---------------- K4: scatter combine/dispatch + l_aux + exp_counts -------
__global__ __launch_bounds__(256)
void k4_final(float* __restrict__ laux, float* __restrict__ cw,
              float* __restrict__ dm,   float* __restrict__ ec)
{
    __shared__ float rs[8][32];
    __shared__ int   rc[8][32];

    if (blockIdx.x == 0) {
        // parallel reduction of per-block partial gate sums / counts
        int e  = threadIdx.x & 31;
        int ch = threadIdx.x >> 5;       // 0..7
        float s = 0.f; int c = 0;
        for (int b = ch; b < NB2; b += 8) {
            s += g_pgsum[b * E + e];
            c += g_pcnt [b * E + e];
        }
        rs[ch][e] = s; rc[ch][e] = c;
        __syncthreads();
        if (threadIdx.x < 32) {
            float st = 0.f; int ct = 0;
#pragma unroll
            for (int k = 0; k < 8; k++) { st += rs[k][threadIdx.x]; ct += rc[k][threadIdx.x]; }
            if (ec) ec[threadIdx.x] = (float)ct;
            float prod = (st / (float)S) * ((float)ct / (float)S);
#pragma unroll
            for (int off = 16; off; off >>= 1) prod += __shfl_xor_sync(0xffffffffu, prod, off);
            if (threadIdx.x == 0 && laux) laux[0] = prod * 16.0f;   // *E*E/K/E = *16
        }
    }

    int t = blockIdx.x * 256 + threadIdx.x;
    if (t >= S) return;

    int   i1 = g_top_i1[t], i2 = g_top_i2[t];
    float g1 = g_top_g1[t], g2 = g_top_g2[t];
    int   s1 = g_slot[2 * t], s2 = g_slot[2 * t + 1];
    bool  k1 = (s1 >= 0), k2 = (s2 >= 0);

    float denom = (k1 ? g1 : 0.f) + (k2 ? g2 : 0.f);
    if (denom <= 0.f) return;

    int c = (k1 ? s1 : 0) + (k2 ? s2 : 0);   // locations_s = SUM of slots (ref semantics)
    if (c >= CAP) return;                     // one_hot out of range -> all zeros

    if (k1 && cw) {
        size_t o = ((size_t)t * E + i1) * CAP + c;
        cw[o] = g1 / denom;
        if (dm) dm[o] = 1.0f;
    }
    if (k2 && cw) {
        size_t o = ((size_t)t * E + i2) * CAP + c;
        cw[o] = g2 / denom;
        if (dm) dm[o] = 1.0f;
    }
}

// ---------------- launch ---------------------------------------------------
extern "C" void kernel_launch(void* const* d_in, const int* in_sizes, int n_in,
                              void* d_out, int out_size)
{
    const float* x  = (const float*)d_in[0];
    const float* wg = (const float*)d_in[1];
    float* out = (float*)d_out;

    const long long CW = (long long)CW_ELEMS;
    float *laux = nullptr, *cw = nullptr, *dm = nullptr, *ec = nullptr;

    long long osz = (long long)out_size;
    if (osz == 1 + 2 * CW + 32) {
        laux = out;
        cw   = out + 1;
        dm   = out + 1 + CW;
        ec   = out + 1 + 2 * CW;
    } else if (osz == 2 * CW) {
        cw = out; dm = out + CW;
    } else if (osz == CW) {
        cw = out;
    } else {
        laux = out;
        cw   = out + 1;
        if (osz > 1 + CW)     dm = out + 1 + CW;
        if (osz > 1 + 2 * CW) ec = out + 1 + 2 * CW;
    }

    k1_gemm_fill<<<GEMM_BLOCKS + FILL_BLOCKS, K1_THREADS>>>(x, wg, out, osz);
    k3_capacity<<<E, 256>>>();
    k4_final<<<(S + 255) / 256, 256>>>(laux, cw, dm, ec);
}

// round 5
// speedup vs baseline: 1.2249x; 1.1769x over previous
#include <cuda_runtime.h>
#include <math.h>
#include <float.h>
#include <stdint.h>

#define S   4096
#define MD  2048
#define E   32
#define CAP 256
#define CW_ELEMS ((size_t)S * E * CAP)   // 33554432

// ---------------- device scratch (no allocations allowed) ----------------
__device__ int   g_top_i1[S];
__device__ int   g_top_i2[S];
__device__ float g_top_v1[S];
__device__ float g_top_v2[S];
__device__ float g_top_g1[S];
__device__ float g_top_g2[S];
__device__ int   g_slot[S * 2];

#define GEMM_BLOCKS 128
#define NB2 GEMM_BLOCKS
__device__ float g_pgsum[NB2 * E];
__device__ int   g_pcnt[NB2 * E];

// ---------------- K1: GEMM (logits = x @ wg^T) + top2/softmax epilogue ----
#define K1_THREADS  128
#define KC 128
#define LD4 33   // float4 row stride (shifts banks)

__global__ __launch_bounds__(K1_THREADS)
void k1_gemm(const float* __restrict__ x, const float* __restrict__ wg)
{
    // ---- GEMM: 32 tokens x 32 experts per block, K-chunks of 128 ----
    __shared__ float4 xs[32 * LD4];
    __shared__ float4 ws[32 * LD4];
    __shared__ float  ps[4][32];
    __shared__ int    pc[4][32];

    const int tid = threadIdx.x;
    const int tx  = tid & 7;    // expert group (4 experts)
    const int ty  = tid >> 3;   // token group  (2 tokens), 0..15
    const int t0  = blockIdx.x * 32;

    float acc[2][4];
#pragma unroll
    for (int i = 0; i < 2; i++)
#pragma unroll
        for (int j = 0; j < 4; j++) acc[i][j] = 0.f;

    const float4* x4 = (const float4*)x;
    const float4* w4 = (const float4*)wg;

    for (int kc = 0; kc < MD; kc += KC) {
        const int kc4 = kc >> 2;
        for (int i = tid; i < 32 * 32; i += K1_THREADS) {
            int r = i >> 5, c = i & 31;
            xs[r * LD4 + c] = x4[(size_t)(t0 + r) * (MD / 4) + kc4 + c];
            ws[r * LD4 + c] = w4[(size_t)r       * (MD / 4) + kc4 + c];
        }
        __syncthreads();

#pragma unroll 8
        for (int k4 = 0; k4 < 32; k4++) {
            float4 a0 = xs[(2 * ty)     * LD4 + k4];
            float4 a1 = xs[(2 * ty + 1) * LD4 + k4];
#pragma unroll
            for (int j = 0; j < 4; j++) {
                float4 b = ws[(4 * tx + j) * LD4 + k4];
                acc[0][j] = fmaf(a0.x, b.x, fmaf(a0.y, b.y, fmaf(a0.z, b.z, fmaf(a0.w, b.w, acc[0][j]))));
                acc[1][j] = fmaf(a1.x, b.x, fmaf(a1.y, b.y, fmaf(a1.z, b.z, fmaf(a1.w, b.w, acc[1][j]))));
            }
        }
        __syncthreads();
    }

    // ---- epilogue: stash logits in smem (reuse xs), then top2+softmax ----
    float* lg = (float*)xs;   // [32][33] floats
#pragma unroll
    for (int i = 0; i < 2; i++)
#pragma unroll
        for (int j = 0; j < 4; j++)
            lg[(2 * ty + i) * 33 + (4 * tx + j)] = acc[i][j];
    __syncthreads();

    const int warp = tid >> 5;
    const int lane = tid & 31;
    float gsum = 0.f;
    int   gcnt = 0;

#pragma unroll
    for (int k = 0; k < 8; k++) {
        const int tl = warp * 8 + k;
        const int t  = t0 + tl;
        float l = lg[tl * 33 + lane];

        // top-1 (tie -> lower index, matching jax.lax.top_k)
        float v1 = l; int i1 = lane;
#pragma unroll
        for (int off = 16; off; off >>= 1) {
            float ov = __shfl_xor_sync(0xffffffffu, v1, off);
            int   oi = __shfl_xor_sync(0xffffffffu, i1, off);
            if (ov > v1 || (ov == v1 && oi < i1)) { v1 = ov; i1 = oi; }
        }
        // top-2
        float l2 = (lane == i1) ? -FLT_MAX : l;
        float v2 = l2; int i2 = lane;
#pragma unroll
        for (int off = 16; off; off >>= 1) {
            float ov = __shfl_xor_sync(0xffffffffu, v2, off);
            int   oi = __shfl_xor_sync(0xffffffffu, i2, off);
            if (ov > v2 || (ov == v2 && oi < i2)) { v2 = ov; i2 = oi; }
        }

        // softmax over the 32 logits
        float p = expf(l - v1);
        float sum = p;
#pragma unroll
        for (int off = 16; off; off >>= 1) sum += __shfl_xor_sync(0xffffffffu, sum, off);
        float gate = p / sum;

        float g1v = __shfl_sync(0xffffffffu, gate, i1);
        float g2v = __shfl_sync(0xffffffffu, gate, i2);

        if (lane == 0) {
            g_top_i1[t] = i1;  g_top_i2[t] = i2;
            g_top_v1[t] = v1;  g_top_v2[t] = v2;
            g_top_g1[t] = g1v; g_top_g2[t] = g2v;
            g_slot[2 * t]     = -1;
            g_slot[2 * t + 1] = -1;
        }

        gsum += gate;
        gcnt += (i1 == lane) + (i2 == lane);
    }

    ps[warp][lane] = gsum;
    pc[warp][lane] = gcnt;
    __syncthreads();
    if (tid < 32) {
        float s = ps[0][tid] + ps[1][tid] + ps[2][tid] + ps[3][tid];
        int   c = pc[0][tid] + pc[1][tid] + pc[2][tid] + pc[3][tid];
        g_pgsum[blockIdx.x * E + tid] = s;
        g_pcnt [blockIdx.x * E + tid] = c;
    }
}

// ---------------- K3: per-expert capacity filter + slot assignment --------
__global__ __launch_bounds__(256)
void k3_capacity()
{
    const int e = blockIdx.x;
    __shared__ float vals[S];
    __shared__ int   s_cnt;
    __shared__ float s_thr;
    __shared__ int   warp_tot[8];
    __shared__ int   s_running;

    if (threadIdx.x == 0) { s_cnt = 0; s_running = 0; }
    __syncthreads();

    // gather positive selected logits for this expert
    for (int t = threadIdx.x; t < S; t += 256) {
        int i1 = g_top_i1[t], i2 = g_top_i2[t];
        float v; int hit = 0;
        if (i1 == e)      { v = g_top_v1[t]; hit = 1; }
        else if (i2 == e) { v = g_top_v2[t]; hit = 1; }
        else v = 0.f;
        if (hit && v > 0.f) {
            int p = atomicAdd(&s_cnt, 1);
            vals[p] = v;
        }
    }
    __syncthreads();

    int n = s_cnt;
    if (n <= CAP) {
        if (threadIdx.x == 0) s_thr = -FLT_MAX;
        __syncthreads();
    } else {
        int n2 = 1; while (n2 < n) n2 <<= 1;
        for (int i = n + threadIdx.x; i < n2; i += 256) vals[i] = -FLT_MAX;
        __syncthreads();
        // bitonic sort, descending
        for (int k = 2; k <= n2; k <<= 1) {
            for (int j = k >> 1; j > 0; j >>= 1) {
                for (int i = threadIdx.x; i < n2; i += 256) {
                    int ixj = i ^ j;
                    if (ixj > i) {
                        float a = vals[i], b = vals[ixj];
                        bool desc = ((i & k) == 0);
                        if (desc ? (a < b) : (a > b)) { vals[i] = b; vals[ixj] = a; }
                    }
                }
                __syncthreads();
            }
        }
        if (threadIdx.x == 0) s_thr = vals[CAP - 1];
        __syncthreads();
    }
    float thr = s_thr;

    // token-order scan: assign cumulative slots
    const int lane = threadIdx.x & 31;
    const int w    = threadIdx.x >> 5;
    for (int base = 0; base < S; base += 256) {
        int t = base + threadIdx.x;
        int i1 = g_top_i1[t], i2 = g_top_i2[t];
        int j = (i1 == e) ? 0 : ((i2 == e) ? 1 : -1);
        float v = (j == 0) ? g_top_v1[t] : ((j == 1) ? g_top_v2[t] : 0.f);
        int kept = (j >= 0 && v > 0.f && v >= thr) ? 1 : 0;

        unsigned bal = __ballot_sync(0xffffffffu, kept);
        int pre = __popc(bal & ((1u << lane) - 1u));
        if (lane == 31) warp_tot[w] = pre + kept;
        __syncthreads();

        int woff = 0;
#pragma unroll
        for (int ww = 0; ww < 8; ww++) woff += (ww < w) ? warp_tot[ww] : 0;
        int slot = s_running + woff + pre;
        if (kept) g_slot[2 * t + j] = slot;
        __syncthreads();

        if (threadIdx.x == 0) {
            int tot = 0;
#pragma unroll
            for (int ww = 0; ww < 8; ww++) tot += warp_tot[ww];
            s_running += tot;
        }
        __syncthreads();
    }
}

// ---------------- K4: scatter combine/dispatch + l_aux + exp_counts -------
__global__ __launch_bounds__(256)
void k4_final(float* __restrict__ laux, float* __restrict__ cw,
              float* __restrict__ dm,   float* __restrict__ ec)
{
    __shared__ float rs[8][32];
    __shared__ int   rc[8][32];

    if (blockIdx.x == 0) {
        // parallel reduction of per-block partial gate sums / counts
        int e  = threadIdx.x & 31;
        int ch = threadIdx.x >> 5;       // 0..7
        float s = 0.f; int c = 0;
        for (int b = ch; b < NB2; b += 8) {
            s += g_pgsum[b * E + e];
            c += g_pcnt [b * E + e];
        }
        rs[ch][e] = s; rc[ch][e] = c;
        __syncthreads();
        if (threadIdx.x < 32) {
            float st = 0.f; int ct = 0;
#pragma unroll
            for (int k = 0; k < 8; k++) { st += rs[k][threadIdx.x]; ct += rc[k][threadIdx.x]; }
            if (ec) ec[threadIdx.x] = (float)ct;
            float prod = (st / (float)S) * ((float)ct / (float)S);
#pragma unroll
            for (int off = 16; off; off >>= 1) prod += __shfl_xor_sync(0xffffffffu, prod, off);
            if (threadIdx.x == 0 && laux) laux[0] = prod * 16.0f;   // *E*E/K/E = *16
        }
    }

    int t = blockIdx.x * 256 + threadIdx.x;
    if (t >= S) return;

    int   i1 = g_top_i1[t], i2 = g_top_i2[t];
    float g1 = g_top_g1[t], g2 = g_top_g2[t];
    int   s1 = g_slot[2 * t], s2 = g_slot[2 * t + 1];
    bool  k1 = (s1 >= 0), k2 = (s2 >= 0);

    float denom = (k1 ? g1 : 0.f) + (k2 ? g2 : 0.f);
    if (denom <= 0.f) return;

    int c = (k1 ? s1 : 0) + (k2 ? s2 : 0);   // locations_s = SUM of slots (ref semantics)
    if (c >= CAP) return;                     // one_hot out of range -> all zeros

    if (k1 && cw) {
        size_t o = ((size_t)t * E + i1) * CAP + c;
        cw[o] = g1 / denom;
        if (dm) dm[o] = 1.0f;
    }
    if (k2 && cw) {
        size_t o = ((size_t)t * E + i2) * CAP + c;
        cw[o] = g2 / denom;
        if (dm) dm[o] = 1.0f;
    }
}

// ---------------- launch ---------------------------------------------------
extern "C" void kernel_launch(void* const* d_in, const int* in_sizes, int n_in,
                              void* d_out, int out_size)
{
    const float* x  = (const float*)d_in[0];
    const float* wg = (const float*)d_in[1];
    float* out = (float*)d_out;

    const long long CW = (long long)CW_ELEMS;
    float *laux = nullptr, *cw = nullptr, *dm = nullptr, *ec = nullptr;

    long long osz = (long long)out_size;
    if (osz == 1 + 2 * CW + 32) {
        laux = out;
        cw   = out + 1;
        dm   = out + 1 + CW;
        ec   = out + 1 + 2 * CW;
    } else if (osz == 2 * CW) {
        cw = out; dm = out + CW;
    } else if (osz == CW) {
        cw = out;
    } else {
        laux = out;
        cw   = out + 1;
        if (osz > 1 + CW)     dm = out + 1 + CW;
        if (osz > 1 + 2 * CW) ec = out + 1 + 2 * CW;
    }

    // Driver-optimized zero-fill of the whole output (graph-capturable memset
    // node; ~4.5-5.5 TB/s vs 1.4 TB/s for the previous in-kernel fill).
    cudaMemsetAsync(out, 0, (size_t)osz * sizeof(float), 0);

    k1_gemm<<<GEMM_BLOCKS, K1_THREADS>>>(x, wg);
    k3_capacity<<<E, 256>>>();
    k4_final<<<(S + 255) / 256, 256>>>(laux, cw, dm, ec);
}